// round 15
// baseline (speedup 1.0000x reference)
#include <cuda_runtime.h>
#include <cuda_fp16.h>
#include <cstdint>
#include <cstddef>

// GhostLinear: out = x @ (lut[gi]*scale)^T.  M=8192, N=4096, K=4096.
// R14: mbarrier producer/consumer pipeline WITHOUT cp.async.mbarrier.arrive
// (that instruction deadlocked on sm_103 in R12/R13). Visibility chain:
// per-thread cp.async.wait_group -> mbarrier.arrive(release) -> try_wait(acquire).
// One commit per iteration (empty commits at tail) keeps group accounting uniform.

#define M_DIM 8192
#define N_DIM 4096
#define K_DIM 4096

#define BM 128
#define BN 128
#define BK 64
#define NSTAGES 3
#define NK (K_DIM / BK)                 // 64

#define TILE_BYTES (128 * 128)          // 128 rows x 64 halfs (128B)
#define STAGE_BYTES (2 * TILE_BYTES)    // A + B = 32768
#define SMEM_DYN (NSTAGES * STAGE_BYTES)  // 98304

// Scratch (device globals: allocation-free): W fp16 (32MB) + X fp16 (64MB)
__device__ __half g_Wh[(size_t)N_DIM * (size_t)K_DIM];
__device__ __half g_Xh[(size_t)M_DIM * (size_t)K_DIM];

__device__ __forceinline__ uint32_t smem_u32(const void* p) {
    uint32_t a;
    asm("{ .reg .u64 t; cvta.to.shared.u64 t, %1; cvt.u32.u64 %0, t; }"
        : "=r"(a) : "l"(p));
    return a;
}

#define CP_ASYNC16(smem, gmem) \
    asm volatile("cp.async.cg.shared.global [%0], [%1], 16;" :: "r"(smem), "l"(gmem) : "memory")
#define CP_COMMIT() asm volatile("cp.async.commit_group;" ::: "memory")
#define CP_WAIT(n)  asm volatile("cp.async.wait_group %0;" :: "n"(n) : "memory")

#define MBARRIER_INIT(addr, cnt) \
    asm volatile("mbarrier.init.shared.b64 [%0], %1;" :: "r"(addr), "r"((uint32_t)(cnt)) : "memory")

#define MBAR_ARRIVE(addr) \
    asm volatile("mbarrier.arrive.release.cta.shared::cta.b64 _, [%0];" :: "r"(addr) : "memory")

#define MBAR_WAIT(addr, parity) do {                                                   \
    uint32_t _done;                                                                     \
    asm volatile(                                                                       \
        "{\n\t.reg .pred p;\n\t"                                                        \
        "mbarrier.try_wait.parity.acquire.cta.shared::cta.b64 p, [%1], %2;\n\t"        \
        "selp.b32 %0, 1, 0, p;\n\t}"                                                    \
        : "=r"(_done) : "r"(addr), "r"((uint32_t)(parity)) : "memory");                 \
    if (!_done) {                                                                       \
        asm volatile(                                                                   \
            "{\n\t.reg .pred P1;\n\t"                                                   \
            "WL_%=:\n\t"                                                                \
            "mbarrier.try_wait.parity.acquire.cta.shared::cta.b64 P1, [%0], %1, 0x989680;\n\t" \
            "@P1 bra.uni WD_%=;\n\t"                                                    \
            "bra.uni WL_%=;\n\t"                                                        \
            "WD_%=:\n\t}"                                                               \
            :: "r"(addr), "r"((uint32_t)(parity)) : "memory");                          \
    }                                                                                   \
} while (0)

#define LDSM_X4(r0, r1, r2, r3, addr) \
    asm volatile("ldmatrix.sync.aligned.m8n8.x4.shared.b16 {%0,%1,%2,%3}, [%4];" \
                 : "=r"(r0), "=r"(r1), "=r"(r2), "=r"(r3) : "r"(addr))

__device__ __forceinline__ void mma_f16(float& c0, float& c1, float& c2, float& c3,
                                        uint32_t a0, uint32_t a1, uint32_t a2, uint32_t a3,
                                        uint32_t b0, uint32_t b1) {
    asm volatile(
        "mma.sync.aligned.m16n8k16.row.col.f32.f16.f16.f32 "
        "{%0,%1,%2,%3}, {%4,%5,%6,%7}, {%8,%9}, {%0,%1,%2,%3};"
        : "+f"(c0), "+f"(c1), "+f"(c2), "+f"(c3)
        : "r"(a0), "r"(a1), "r"(a2), "r"(a3), "r"(b0), "r"(b1));
}

// ---------------------------------------------------------------------------
// Fused prep: blocks [0, 8192) dequant W; blocks [8192, 24576) convert X.
// ---------------------------------------------------------------------------
__global__ void __launch_bounds__(256) ghost_prep(const int4* __restrict__ gi,
                                                  const float* __restrict__ lut,
                                                  const float* __restrict__ scale,
                                                  const float4* __restrict__ X) {
    const unsigned b = blockIdx.x;
    if (b < 8192u) {
        unsigned i = b * 256u + threadIdx.x;           // W 8-pack index
        int4 v0 = gi[2 * i];
        int4 v1 = gi[2 * i + 1];
        float s = __ldg(&scale[i >> 9]);
        __half2 h0 = __floats2half2_rn(__ldg(&lut[v0.x]) * s, __ldg(&lut[v0.y]) * s);
        __half2 h1 = __floats2half2_rn(__ldg(&lut[v0.z]) * s, __ldg(&lut[v0.w]) * s);
        __half2 h2 = __floats2half2_rn(__ldg(&lut[v1.x]) * s, __ldg(&lut[v1.y]) * s);
        __half2 h3 = __floats2half2_rn(__ldg(&lut[v1.z]) * s, __ldg(&lut[v1.w]) * s);
        uint4 w;
        w.x = *(uint32_t*)&h0; w.y = *(uint32_t*)&h1;
        w.z = *(uint32_t*)&h2; w.w = *(uint32_t*)&h3;
        reinterpret_cast<uint4*>(g_Wh)[i] = w;
    } else {
        unsigned i = (b - 8192u) * 256u + threadIdx.x; // X 8-pack index
        float4 f0 = X[2 * i];
        float4 f1 = X[2 * i + 1];
        __half2 h0 = __floats2half2_rn(f0.x, f0.y);
        __half2 h1 = __floats2half2_rn(f0.z, f0.w);
        __half2 h2 = __floats2half2_rn(f1.x, f1.y);
        __half2 h3 = __floats2half2_rn(f1.z, f1.w);
        uint4 w;
        w.x = *(uint32_t*)&h0; w.y = *(uint32_t*)&h1;
        w.z = *(uint32_t*)&h2; w.w = *(uint32_t*)&h3;
        reinterpret_cast<uint4*>(g_Xh)[i] = w;
    }
}

// ---------------------------------------------------------------------------
// GEMM: Out[M,N] = Xh[M,K] * Wh[N,K]^T
// 256 threads = 8 warps (2m x 4n), warp tile 64x32, mma m16n8k16 f16->f32.
// smem row = 64 halfs (128B = 8 x 16B chunks); SW128 swizzle: chunk ^= (row&7).
// Sync: per-stage full/empty mbarriers; no bar.sync in the mainloop.
//   iter kt: [wait empty(ps); issue cp.async ps] -> commit (always) ->
//            cp.async.wait_group 2 -> arrive full(cs) -> wait full(cs) ->
//            consume cs -> arrive empty(cs)
// ---------------------------------------------------------------------------
__global__ void __launch_bounds__(256, 2) ghost_gemm(float* __restrict__ Out) {
    extern __shared__ char dynsmem[];
    __shared__ unsigned long long mbar[2 * NSTAGES];   // full[0..2], empty[0..2]

    const int tid = threadIdx.x;
    const int lane = tid & 31;
    const int wid = tid >> 5;
    const int wm = wid >> 2;              // 0..1
    const int wn = wid & 3;               // 0..3
    const int g = lane >> 2;              // 0..7
    const int t = lane & 3;               // 0..3

    const int n0 = blockIdx.x * BN;
    const int m0 = blockIdx.y * BM;

    const uint32_t sbase = smem_u32(dynsmem);
    const uint32_t mb = smem_u32(&mbar[0]);
    // full[s] = mb + 8*s ; empty[s] = mb + 8*(NSTAGES+s)

    if (tid == 0) {
        #pragma unroll
        for (int s = 0; s < 2 * NSTAGES; s++) MBARRIER_INIT(mb + 8 * s, 256);
    }
    __syncthreads();   // only CTA barrier: publish mbarrier init

    // ---- cp.async geometry: 4 chunks/thread per tile per stage ----
    const int cprow = tid >> 3;                        // 0..31
    const int cpc = tid & 7;
    const uint32_t cpOff0 = (uint32_t)(cprow * 128 + ((cpc ^ (cprow & 7)) << 4));
    const __half* gAb = g_Xh + (size_t)(m0 + cprow) * K_DIM + cpc * 8;
    const __half* gBb = g_Wh + (size_t)(n0 + cprow) * K_DIM + cpc * 8;

    // ---- prologue: fill stages 0,1 (one commit each) ----
    #pragma unroll
    for (int c = 0; c < NSTAGES - 1; c++) {
        uint32_t ab = sbase + c * STAGE_BYTES;
        uint32_t bb = ab + TILE_BYTES;
        int koff = c * BK;
        #pragma unroll
        for (int j = 0; j < 4; j++) {
            CP_ASYNC16(ab + cpOff0 + j * 4096, gAb + (size_t)j * 32 * K_DIM + koff);
            CP_ASYNC16(bb + cpOff0 + j * 4096, gBb + (size_t)j * 32 * K_DIM + koff);
        }
        CP_COMMIT();
    }

    // ---- ldmatrix per-thread address pieces ----
    const int q = lane >> 3;
    const int r = lane & 7;
    const uint32_t aRB = (uint32_t)(wm * 64 + (q & 1) * 8 + r) * 128;
    const uint32_t bRB = (uint32_t)(wn * 32 + (q >> 1) * 8 + r) * 128;
    const uint32_t aCQ = (uint32_t)(q >> 1);
    const uint32_t bCQ = (uint32_t)(q & 1);

    float acc[4][4][4];
    #pragma unroll
    for (int i = 0; i < 4; i++)
        #pragma unroll
        for (int j = 0; j < 4; j++)
            #pragma unroll
            for (int k2 = 0; k2 < 4; k2++) acc[i][j][k2] = 0.0f;

    // pipeline cursors
    int cs = 0, cph = 0;                  // consumer stage, full-parity round bit
    int ps = NSTAGES - 1, pround = 0;     // producer stage, fill round

    #pragma unroll 1
    for (int kt = 0; kt < NK; kt++) {
        // ---- producer: fill stage ps with chunk kt+2 (if any) ----
        if (kt < NK - (NSTAGES - 1)) {
            if (pround >= 1) MBAR_WAIT(mb + 8 * (NSTAGES + ps), (pround - 1) & 1);
            uint32_t ab = sbase + ps * STAGE_BYTES;
            uint32_t bb = ab + TILE_BYTES;
            int koff = (kt + NSTAGES - 1) * BK;
            #pragma unroll
            for (int j = 0; j < 4; j++) {
                CP_ASYNC16(ab + cpOff0 + j * 4096, gAb + (size_t)j * 32 * K_DIM + koff);
                CP_ASYNC16(bb + cpOff0 + j * 4096, gBb + (size_t)j * 32 * K_DIM + koff);
            }
            if (++ps == NSTAGES) { ps = 0; pround++; }
        }
        CP_COMMIT();   // ALWAYS one group per iteration (empty at tail) -> uniform accounting

        // ---- certify own copies for stage cs (committed 2 groups ago), publish, gather ----
        CP_WAIT(2);
        MBAR_ARRIVE(mb + 8 * cs);              // release my cp.async writes
        MBAR_WAIT(mb + 8 * cs, cph);           // acquire everyone's

        const uint32_t aTile = sbase + cs * STAGE_BYTES;
        const uint32_t bTile = aTile + TILE_BYTES;

        #pragma unroll
        for (int ks = 0; ks < 4; ks++) {
            const uint32_t cA = ((uint32_t)(ks * 2) + aCQ) ^ (uint32_t)r;
            const uint32_t cB = ((uint32_t)(ks * 2) + bCQ) ^ (uint32_t)r;

            uint32_t a[4][4];
            #pragma unroll
            for (int mt = 0; mt < 4; mt++) {
                uint32_t addr = aTile + aRB + (uint32_t)(mt * 2048) + (cA << 4);
                LDSM_X4(a[mt][0], a[mt][1], a[mt][2], a[mt][3], addr);
            }
            uint32_t b[2][4];
            #pragma unroll
            for (int nt2 = 0; nt2 < 2; nt2++) {
                uint32_t addr = bTile + bRB + (uint32_t)(nt2 * 2048) + (cB << 4);
                LDSM_X4(b[nt2][0], b[nt2][1], b[nt2][2], b[nt2][3], addr);
            }

            #pragma unroll
            for (int mt = 0; mt < 4; mt++) {
                #pragma unroll
                for (int nt = 0; nt < 4; nt++) {
                    mma_f16(acc[mt][nt][0], acc[mt][nt][1], acc[mt][nt][2], acc[mt][nt][3],
                            a[mt][0], a[mt][1], a[mt][2], a[mt][3],
                            b[nt >> 1][2 * (nt & 1)], b[nt >> 1][2 * (nt & 1) + 1]);
                }
            }
        }

        // ---- release stage cs ----
        MBAR_ARRIVE(mb + 8 * (NSTAGES + cs));
        if (++cs == NSTAGES) { cs = 0; cph ^= 1; }
    }

    // ---- epilogue: direct float2 stores (c0,c1 at row g; c2,c3 at row g+8) ----
    #pragma unroll
    for (int mt = 0; mt < 4; mt++) {
        int rbase = m0 + wm * 64 + mt * 16 + g;
        #pragma unroll
        for (int nt = 0; nt < 4; nt++) {
            int col = n0 + wn * 32 + nt * 8 + 2 * t;
            *(float2*)(Out + (size_t)rbase * N_DIM + col) =
                make_float2(acc[mt][nt][0], acc[mt][nt][1]);
            *(float2*)(Out + (size_t)(rbase + 8) * N_DIM + col) =
                make_float2(acc[mt][nt][2], acc[mt][nt][3]);
        }
    }
}

// ---------------------------------------------------------------------------
// Launch
// ---------------------------------------------------------------------------
extern "C" void kernel_launch(void* const* d_in, const int* in_sizes, int n_in,
                              void* d_out, int out_size) {
    const float* x   = (const float*)d_in[0];   // [4, 2048, 4096] f32
    const int*   gi  = (const int*)d_in[1];     // [4096, 4096] i32
    const float* lut = (const float*)d_in[2];   // [65536] f32
    const float* sc  = (const float*)d_in[3];   // [4096, 1] f32
    float* out = (float*)d_out;                 // [4, 2048, 4096] f32

    (void)in_sizes; (void)n_in; (void)out_size;

    ghost_prep<<<24576, 256>>>((const int4*)gi, lut, sc, (const float4*)x);

    cudaFuncSetAttribute(ghost_gemm, cudaFuncAttributeMaxDynamicSharedMemorySize, SMEM_DYN);
    ghost_gemm<<<dim3(N_DIM / BN, M_DIM / BM), 256, SMEM_DYN>>>(out);
}

// round 16
// speedup vs baseline: 1.2935x; 1.2935x over previous
#include <cuda_runtime.h>
#include <cuda_fp16.h>
#include <cstdint>
#include <cstddef>

// GhostLinear: out = x @ (lut[gi]*scale)^T.  M=8192, N=4096, K=4096.
// FINAL (= R11, measured best 670.2us): fp16 mma.m16n8k16 + ldmatrix GEMM,
// BM=BN=128, BK=64, 8 warps (2m x 4n) x 64x32 warp tile, 2 CTA/SM,
// 3-stage cp.async ring with bar.sync, top-of-loop prefetch; fused prep
// (dequant W || convert X) in one launch.
//
// Experiment log (why this shape):
//  - tcgen05/TMEM unavailable: harness compiles at compute_103 (no 'a').
//  - fp16 == tf32 mantissa (10 bits): rel_err 2.94e-4 both; fp16 is 2x rate.
//  - 2 CTA/SM mandatory: 1-CTA shapes (R5, R9) regress 15-60% (no cross-CTA
//    stall covering at the per-iter barrier).
//  - spread prefetch (R8) regresses: LDGSTS/LDSM issue contention.
//  - mbarrier pipelines: cp.async.mbarrier.arrive deadlocks on sm_103 (R13);
//    manual 256-arrival mbarriers cost ~440cyc/iter extra (R15). bar.sync wins.

#define M_DIM 8192
#define N_DIM 4096
#define K_DIM 4096

#define BM 128
#define BN 128
#define BK 64
#define NSTAGES 3
#define NK (K_DIM / BK)                 // 64

#define TILE_BYTES (128 * 128)          // 128 rows x 64 halfs (128B)
#define STAGE_BYTES (2 * TILE_BYTES)    // A + B = 32768
#define SMEM_DYN (NSTAGES * STAGE_BYTES)  // 98304

// Scratch (device globals: allocation-free): W fp16 (32MB) + X fp16 (64MB)
__device__ __half g_Wh[(size_t)N_DIM * (size_t)K_DIM];
__device__ __half g_Xh[(size_t)M_DIM * (size_t)K_DIM];

__device__ __forceinline__ uint32_t smem_u32(const void* p) {
    uint32_t a;
    asm("{ .reg .u64 t; cvta.to.shared.u64 t, %1; cvt.u32.u64 %0, t; }"
        : "=r"(a) : "l"(p));
    return a;
}

#define CP_ASYNC16(smem, gmem) \
    asm volatile("cp.async.cg.shared.global [%0], [%1], 16;" :: "r"(smem), "l"(gmem) : "memory")
#define CP_COMMIT() asm volatile("cp.async.commit_group;" ::: "memory")
#define CP_WAIT(n)  asm volatile("cp.async.wait_group %0;" :: "n"(n) : "memory")

#define LDSM_X4(r0, r1, r2, r3, addr) \
    asm volatile("ldmatrix.sync.aligned.m8n8.x4.shared.b16 {%0,%1,%2,%3}, [%4];" \
                 : "=r"(r0), "=r"(r1), "=r"(r2), "=r"(r3) : "r"(addr))

__device__ __forceinline__ void mma_f16(float& c0, float& c1, float& c2, float& c3,
                                        uint32_t a0, uint32_t a1, uint32_t a2, uint32_t a3,
                                        uint32_t b0, uint32_t b1) {
    asm volatile(
        "mma.sync.aligned.m16n8k16.row.col.f32.f16.f16.f32 "
        "{%0,%1,%2,%3}, {%4,%5,%6,%7}, {%8,%9}, {%0,%1,%2,%3};"
        : "+f"(c0), "+f"(c1), "+f"(c2), "+f"(c3)
        : "r"(a0), "r"(a1), "r"(a2), "r"(a3), "r"(b0), "r"(b1));
}

// ---------------------------------------------------------------------------
// Fused prep: blocks [0, 8192) dequant W; blocks [8192, 24576) convert X.
// dequant is L2-gather-bound, xconv is DRAM-stream-bound -> overlap them.
// ---------------------------------------------------------------------------
__global__ void __launch_bounds__(256) ghost_prep(const int4* __restrict__ gi,
                                                  const float* __restrict__ lut,
                                                  const float* __restrict__ scale,
                                                  const float4* __restrict__ X) {
    const unsigned b = blockIdx.x;
    if (b < 8192u) {
        unsigned i = b * 256u + threadIdx.x;           // W 8-pack index
        int4 v0 = gi[2 * i];
        int4 v1 = gi[2 * i + 1];
        float s = __ldg(&scale[i >> 9]);
        __half2 h0 = __floats2half2_rn(__ldg(&lut[v0.x]) * s, __ldg(&lut[v0.y]) * s);
        __half2 h1 = __floats2half2_rn(__ldg(&lut[v0.z]) * s, __ldg(&lut[v0.w]) * s);
        __half2 h2 = __floats2half2_rn(__ldg(&lut[v1.x]) * s, __ldg(&lut[v1.y]) * s);
        __half2 h3 = __floats2half2_rn(__ldg(&lut[v1.z]) * s, __ldg(&lut[v1.w]) * s);
        uint4 w;
        w.x = *(uint32_t*)&h0; w.y = *(uint32_t*)&h1;
        w.z = *(uint32_t*)&h2; w.w = *(uint32_t*)&h3;
        reinterpret_cast<uint4*>(g_Wh)[i] = w;
    } else {
        unsigned i = (b - 8192u) * 256u + threadIdx.x; // X 8-pack index
        float4 f0 = X[2 * i];
        float4 f1 = X[2 * i + 1];
        __half2 h0 = __floats2half2_rn(f0.x, f0.y);
        __half2 h1 = __floats2half2_rn(f0.z, f0.w);
        __half2 h2 = __floats2half2_rn(f1.x, f1.y);
        __half2 h3 = __floats2half2_rn(f1.z, f1.w);
        uint4 w;
        w.x = *(uint32_t*)&h0; w.y = *(uint32_t*)&h1;
        w.z = *(uint32_t*)&h2; w.w = *(uint32_t*)&h3;
        reinterpret_cast<uint4*>(g_Xh)[i] = w;
    }
}

// ---------------------------------------------------------------------------
// GEMM: Out[M,N] = Xh[M,K] * Wh[N,K]^T
// 256 threads = 8 warps (2m x 4n), warp tile 64x32, mma m16n8k16 f16->f32.
// smem row = 64 halfs (128B = 8 x 16B chunks); SW128 swizzle: chunk ^= (row&7).
// ---------------------------------------------------------------------------
__global__ void __launch_bounds__(256, 2) ghost_gemm(float* __restrict__ Out) {
    extern __shared__ char dynsmem[];

    const int tid = threadIdx.x;
    const int lane = tid & 31;
    const int wid = tid >> 5;
    const int wm = wid >> 2;              // 0..1
    const int wn = wid & 3;               // 0..3
    const int g = lane >> 2;              // 0..7
    const int t = lane & 3;               // 0..3

    const int n0 = blockIdx.x * BN;
    const int m0 = blockIdx.y * BM;

    const uint32_t sbase = smem_u32(dynsmem);

    // ---- cp.async geometry: 4 chunks/thread per tile per stage ----
    // chunk id = tid + 256*j : row = tid>>3 (+32j), c = tid&7
    const int cprow = tid >> 3;                        // 0..31
    const int cpc = tid & 7;
    const uint32_t cpOff0 = (uint32_t)(cprow * 128 + ((cpc ^ (cprow & 7)) << 4));
    const __half* gAb = g_Xh + (size_t)(m0 + cprow) * K_DIM + cpc * 8;
    const __half* gBb = g_Wh + (size_t)(n0 + cprow) * K_DIM + cpc * 8;
    // chunk j: smem += j*4096 ; gmem += j*32*K_DIM

    // ---- prologue: fill 2 stages ----
    #pragma unroll
    for (int c = 0; c < NSTAGES - 1; c++) {
        uint32_t ab = sbase + c * STAGE_BYTES;
        uint32_t bb = ab + TILE_BYTES;
        int koff = c * BK;
        #pragma unroll
        for (int j = 0; j < 4; j++) {
            CP_ASYNC16(ab + cpOff0 + j * 4096, gAb + (size_t)j * 32 * K_DIM + koff);
            CP_ASYNC16(bb + cpOff0 + j * 4096, gBb + (size_t)j * 32 * K_DIM + koff);
        }
        CP_COMMIT();
    }

    // ---- ldmatrix per-thread address pieces ----
    const int q = lane >> 3;              // matrix slot 0..3
    const int r = lane & 7;               // row-within-matrix = swizzle key
    const uint32_t aRB = (uint32_t)(wm * 64 + (q & 1) * 8 + r) * 128;
    const uint32_t bRB = (uint32_t)(wn * 32 + (q >> 1) * 8 + r) * 128;
    const uint32_t aCQ = (uint32_t)(q >> 1);
    const uint32_t bCQ = (uint32_t)(q & 1);

    float acc[4][4][4];
    #pragma unroll
    for (int i = 0; i < 4; i++)
        #pragma unroll
        for (int j = 0; j < 4; j++)
            #pragma unroll
            for (int k2 = 0; k2 < 4; k2++) acc[i][j][k2] = 0.0f;

    #pragma unroll 1
    for (int kt = 0; kt < NK; kt++) {
        if (kt < NK - 1) CP_WAIT(1);
        else             CP_WAIT(0);
        __syncthreads();

        // top-of-loop prefetch for stage kt+2 (slot freed last iteration)
        const int kc = kt + (NSTAGES - 1);
        if (kc < NK) {
            uint32_t ab = sbase + (kc % NSTAGES) * STAGE_BYTES;
            uint32_t bb = ab + TILE_BYTES;
            int koff = kc * BK;
            #pragma unroll
            for (int j = 0; j < 4; j++) {
                CP_ASYNC16(ab + cpOff0 + j * 4096, gAb + (size_t)j * 32 * K_DIM + koff);
                CP_ASYNC16(bb + cpOff0 + j * 4096, gBb + (size_t)j * 32 * K_DIM + koff);
            }
            CP_COMMIT();
        }

        const uint32_t aTile = sbase + (kt % NSTAGES) * STAGE_BYTES;
        const uint32_t bTile = aTile + TILE_BYTES;

        #pragma unroll
        for (int ks = 0; ks < 4; ks++) {              // four k16 steps per BK=64
            const uint32_t cA = ((uint32_t)(ks * 2) + aCQ) ^ (uint32_t)r;
            const uint32_t cB = ((uint32_t)(ks * 2) + bCQ) ^ (uint32_t)r;

            uint32_t a[4][4];
            #pragma unroll
            for (int mt = 0; mt < 4; mt++) {
                uint32_t addr = aTile + aRB + (uint32_t)(mt * 2048) + (cA << 4);
                LDSM_X4(a[mt][0], a[mt][1], a[mt][2], a[mt][3], addr);
            }
            uint32_t b[2][4];
            #pragma unroll
            for (int nt2 = 0; nt2 < 2; nt2++) {
                uint32_t addr = bTile + bRB + (uint32_t)(nt2 * 2048) + (cB << 4);
                LDSM_X4(b[nt2][0], b[nt2][1], b[nt2][2], b[nt2][3], addr);
            }

            #pragma unroll
            for (int mt = 0; mt < 4; mt++) {
                #pragma unroll
                for (int nt = 0; nt < 4; nt++) {
                    mma_f16(acc[mt][nt][0], acc[mt][nt][1], acc[mt][nt][2], acc[mt][nt][3],
                            a[mt][0], a[mt][1], a[mt][2], a[mt][3],
                            b[nt >> 1][2 * (nt & 1)], b[nt >> 1][2 * (nt & 1) + 1]);
                }
            }
        }
    }

    // ---- epilogue: direct float2 stores (c0,c1 at row g; c2,c3 at row g+8) ----
    #pragma unroll
    for (int mt = 0; mt < 4; mt++) {
        int rbase = m0 + wm * 64 + mt * 16 + g;
        #pragma unroll
        for (int nt = 0; nt < 4; nt++) {
            int col = n0 + wn * 32 + nt * 8 + 2 * t;
            *(float2*)(Out + (size_t)rbase * N_DIM + col) =
                make_float2(acc[mt][nt][0], acc[mt][nt][1]);
            *(float2*)(Out + (size_t)(rbase + 8) * N_DIM + col) =
                make_float2(acc[mt][nt][2], acc[mt][nt][3]);
        }
    }
}

// ---------------------------------------------------------------------------
// Launch
// ---------------------------------------------------------------------------
extern "C" void kernel_launch(void* const* d_in, const int* in_sizes, int n_in,
                              void* d_out, int out_size) {
    const float* x   = (const float*)d_in[0];   // [4, 2048, 4096] f32
    const int*   gi  = (const int*)d_in[1];     // [4096, 4096] i32
    const float* lut = (const float*)d_in[2];   // [65536] f32
    const float* sc  = (const float*)d_in[3];   // [4096, 1] f32
    float* out = (float*)d_out;                 // [4, 2048, 4096] f32

    (void)in_sizes; (void)n_in; (void)out_size;

    ghost_prep<<<24576, 256>>>((const int4*)gi, lut, sc, (const float4*)x);

    cudaFuncSetAttribute(ghost_gemm, cudaFuncAttributeMaxDynamicSharedMemorySize, SMEM_DYN);
    ghost_gemm<<<dim3(N_DIM / BN, M_DIM / BM), 256, SMEM_DYN>>>(out);
}

// round 17
// speedup vs baseline: 1.3020x; 1.0066x over previous
#include <cuda_runtime.h>
#include <cuda_fp16.h>
#include <cstdint>
#include <cstddef>

// GhostLinear: out = x @ (lut[gi]*scale)^T.  M=8192, N=4096, K=4096.
// R17 = R11 baseline (670.2us) + two tweaks:
//  1) prep: interleaved W/X block assignment (b%3) for true gather/stream overlap
//  2) GEMM: warp-phase rotation of the k16-step order (anti-phase LDSM bursts)
// GEMM structure otherwise byte-identical to the measured best.

#define M_DIM 8192
#define N_DIM 4096
#define K_DIM 4096

#define BM 128
#define BN 128
#define BK 64
#define NSTAGES 3
#define NK (K_DIM / BK)                 // 64

#define TILE_BYTES (128 * 128)          // 128 rows x 64 halfs (128B)
#define STAGE_BYTES (2 * TILE_BYTES)    // A + B = 32768
#define SMEM_DYN (NSTAGES * STAGE_BYTES)  // 98304

// Scratch (device globals: allocation-free): W fp16 (32MB) + X fp16 (64MB)
__device__ __half g_Wh[(size_t)N_DIM * (size_t)K_DIM];
__device__ __half g_Xh[(size_t)M_DIM * (size_t)K_DIM];

__device__ __forceinline__ uint32_t smem_u32(const void* p) {
    uint32_t a;
    asm("{ .reg .u64 t; cvta.to.shared.u64 t, %1; cvt.u32.u64 %0, t; }"
        : "=r"(a) : "l"(p));
    return a;
}

#define CP_ASYNC16(smem, gmem) \
    asm volatile("cp.async.cg.shared.global [%0], [%1], 16;" :: "r"(smem), "l"(gmem) : "memory")
#define CP_COMMIT() asm volatile("cp.async.commit_group;" ::: "memory")
#define CP_WAIT(n)  asm volatile("cp.async.wait_group %0;" :: "n"(n) : "memory")

#define LDSM_X4(r0, r1, r2, r3, addr) \
    asm volatile("ldmatrix.sync.aligned.m8n8.x4.shared.b16 {%0,%1,%2,%3}, [%4];" \
                 : "=r"(r0), "=r"(r1), "=r"(r2), "=r"(r3) : "r"(addr))

__device__ __forceinline__ void mma_f16(float& c0, float& c1, float& c2, float& c3,
                                        uint32_t a0, uint32_t a1, uint32_t a2, uint32_t a3,
                                        uint32_t b0, uint32_t b1) {
    asm volatile(
        "mma.sync.aligned.m16n8k16.row.col.f32.f16.f16.f32 "
        "{%0,%1,%2,%3}, {%4,%5,%6,%7}, {%8,%9}, {%0,%1,%2,%3};"
        : "+f"(c0), "+f"(c1), "+f"(c2), "+f"(c3)
        : "r"(a0), "r"(a1), "r"(a2), "r"(a3), "r"(b0), "r"(b1));
}

// ---------------------------------------------------------------------------
// Fused prep, interleaved: b%3==0 -> W-dequant (8192 groups), else -> X-conv
// (16384 groups). Mixing the two block types across the whole launch lets the
// L2-gather-latency-bound dequant overlap the DRAM-stream-bound conversion.
// ---------------------------------------------------------------------------
__global__ void __launch_bounds__(256) ghost_prep(const int4* __restrict__ gi,
                                                  const float* __restrict__ lut,
                                                  const float* __restrict__ scale,
                                                  const float4* __restrict__ X) {
    const unsigned b = blockIdx.x;
    const unsigned gph = b / 3u;
    const unsigned rem = b - 3u * gph;
    if (rem == 0u) {
        unsigned i = gph * 256u + threadIdx.x;          // W 8-pack index (0..2097151)
        int4 v0 = gi[2 * i];
        int4 v1 = gi[2 * i + 1];
        float s = __ldg(&scale[i >> 9]);
        __half2 h0 = __floats2half2_rn(__ldg(&lut[v0.x]) * s, __ldg(&lut[v0.y]) * s);
        __half2 h1 = __floats2half2_rn(__ldg(&lut[v0.z]) * s, __ldg(&lut[v0.w]) * s);
        __half2 h2 = __floats2half2_rn(__ldg(&lut[v1.x]) * s, __ldg(&lut[v1.y]) * s);
        __half2 h3 = __floats2half2_rn(__ldg(&lut[v1.z]) * s, __ldg(&lut[v1.w]) * s);
        uint4 w;
        w.x = *(uint32_t*)&h0; w.y = *(uint32_t*)&h1;
        w.z = *(uint32_t*)&h2; w.w = *(uint32_t*)&h3;
        reinterpret_cast<uint4*>(g_Wh)[i] = w;
    } else {
        unsigned i = (gph * 2u + (rem - 1u)) * 256u + threadIdx.x;  // X 8-pack index
        float4 f0 = X[2 * i];
        float4 f1 = X[2 * i + 1];
        __half2 h0 = __floats2half2_rn(f0.x, f0.y);
        __half2 h1 = __floats2half2_rn(f0.z, f0.w);
        __half2 h2 = __floats2half2_rn(f1.x, f1.y);
        __half2 h3 = __floats2half2_rn(f1.z, f1.w);
        uint4 w;
        w.x = *(uint32_t*)&h0; w.y = *(uint32_t*)&h1;
        w.z = *(uint32_t*)&h2; w.w = *(uint32_t*)&h3;
        reinterpret_cast<uint4*>(g_Xh)[i] = w;
    }
}

// ---------------------------------------------------------------------------
// GEMM: Out[M,N] = Xh[M,K] * Wh[N,K]^T
// 256 threads = 8 warps (2m x 4n), warp tile 64x32, mma m16n8k16 f16->f32.
// smem row = 64 halfs (128B = 8 x 16B chunks); SW128 swizzle: chunk ^= (row&7).
// k16-step order rotated per warp: ks = (ks0 + (wid&3)) & 3 (commutative sum).
// ---------------------------------------------------------------------------
__global__ void __launch_bounds__(256, 2) ghost_gemm(float* __restrict__ Out) {
    extern __shared__ char dynsmem[];

    const int tid = threadIdx.x;
    const int lane = tid & 31;
    const int wid = tid >> 5;
    const int wm = wid >> 2;              // 0..1
    const int wn = wid & 3;               // 0..3
    const int g = lane >> 2;              // 0..7
    const int t = lane & 3;               // 0..3
    const int wph = wid & 3;              // warp phase for ks rotation

    const int n0 = blockIdx.x * BN;
    const int m0 = blockIdx.y * BM;

    const uint32_t sbase = smem_u32(dynsmem);

    // ---- cp.async geometry: 4 chunks/thread per tile per stage ----
    const int cprow = tid >> 3;                        // 0..31
    const int cpc = tid & 7;
    const uint32_t cpOff0 = (uint32_t)(cprow * 128 + ((cpc ^ (cprow & 7)) << 4));
    const __half* gAb = g_Xh + (size_t)(m0 + cprow) * K_DIM + cpc * 8;
    const __half* gBb = g_Wh + (size_t)(n0 + cprow) * K_DIM + cpc * 8;
    // chunk j: smem += j*4096 ; gmem += j*32*K_DIM

    // ---- prologue: fill 2 stages ----
    #pragma unroll
    for (int c = 0; c < NSTAGES - 1; c++) {
        uint32_t ab = sbase + c * STAGE_BYTES;
        uint32_t bb = ab + TILE_BYTES;
        int koff = c * BK;
        #pragma unroll
        for (int j = 0; j < 4; j++) {
            CP_ASYNC16(ab + cpOff0 + j * 4096, gAb + (size_t)j * 32 * K_DIM + koff);
            CP_ASYNC16(bb + cpOff0 + j * 4096, gBb + (size_t)j * 32 * K_DIM + koff);
        }
        CP_COMMIT();
    }

    // ---- ldmatrix per-thread address pieces ----
    const int q = lane >> 3;              // matrix slot 0..3
    const int r = lane & 7;               // row-within-matrix = swizzle key
    const uint32_t aRB = (uint32_t)(wm * 64 + (q & 1) * 8 + r) * 128;
    const uint32_t bRB = (uint32_t)(wn * 32 + (q >> 1) * 8 + r) * 128;
    const uint32_t aCQ = (uint32_t)(q >> 1);
    const uint32_t bCQ = (uint32_t)(q & 1);

    float acc[4][4][4];
    #pragma unroll
    for (int i = 0; i < 4; i++)
        #pragma unroll
        for (int j = 0; j < 4; j++)
            #pragma unroll
            for (int k2 = 0; k2 < 4; k2++) acc[i][j][k2] = 0.0f;

    #pragma unroll 1
    for (int kt = 0; kt < NK; kt++) {
        if (kt < NK - 1) CP_WAIT(1);
        else             CP_WAIT(0);
        __syncthreads();

        // top-of-loop prefetch for stage kt+2 (slot freed last iteration)
        const int kc = kt + (NSTAGES - 1);
        if (kc < NK) {
            uint32_t ab = sbase + (kc % NSTAGES) * STAGE_BYTES;
            uint32_t bb = ab + TILE_BYTES;
            int koff = kc * BK;
            #pragma unroll
            for (int j = 0; j < 4; j++) {
                CP_ASYNC16(ab + cpOff0 + j * 4096, gAb + (size_t)j * 32 * K_DIM + koff);
                CP_ASYNC16(bb + cpOff0 + j * 4096, gBb + (size_t)j * 32 * K_DIM + koff);
            }
            CP_COMMIT();
        }

        const uint32_t aTile = sbase + (kt % NSTAGES) * STAGE_BYTES;
        const uint32_t bTile = aTile + TILE_BYTES;

        #pragma unroll
        for (int ks0 = 0; ks0 < 4; ks0++) {           // rotated k16-step order
            const int ks = (ks0 + wph) & 3;
            const uint32_t cA = ((uint32_t)(ks * 2) + aCQ) ^ (uint32_t)r;
            const uint32_t cB = ((uint32_t)(ks * 2) + bCQ) ^ (uint32_t)r;

            uint32_t a[4][4];
            #pragma unroll
            for (int mt = 0; mt < 4; mt++) {
                uint32_t addr = aTile + aRB + (uint32_t)(mt * 2048) + (cA << 4);
                LDSM_X4(a[mt][0], a[mt][1], a[mt][2], a[mt][3], addr);
            }
            uint32_t b[2][4];
            #pragma unroll
            for (int nt2 = 0; nt2 < 2; nt2++) {
                uint32_t addr = bTile + bRB + (uint32_t)(nt2 * 2048) + (cB << 4);
                LDSM_X4(b[nt2][0], b[nt2][1], b[nt2][2], b[nt2][3], addr);
            }

            #pragma unroll
            for (int mt = 0; mt < 4; mt++) {
                #pragma unroll
                for (int nt = 0; nt < 4; nt++) {
                    mma_f16(acc[mt][nt][0], acc[mt][nt][1], acc[mt][nt][2], acc[mt][nt][3],
                            a[mt][0], a[mt][1], a[mt][2], a[mt][3],
                            b[nt >> 1][2 * (nt & 1)], b[nt >> 1][2 * (nt & 1) + 1]);
                }
            }
        }
    }

    // ---- epilogue: direct float2 stores (c0,c1 at row g; c2,c3 at row g+8) ----
    #pragma unroll
    for (int mt = 0; mt < 4; mt++) {
        int rbase = m0 + wm * 64 + mt * 16 + g;
        #pragma unroll
        for (int nt = 0; nt < 4; nt++) {
            int col = n0 + wn * 32 + nt * 8 + 2 * t;
            *(float2*)(Out + (size_t)rbase * N_DIM + col) =
                make_float2(acc[mt][nt][0], acc[mt][nt][1]);
            *(float2*)(Out + (size_t)(rbase + 8) * N_DIM + col) =
                make_float2(acc[mt][nt][2], acc[mt][nt][3]);
        }
    }
}

// ---------------------------------------------------------------------------
// Launch
// ---------------------------------------------------------------------------
extern "C" void kernel_launch(void* const* d_in, const int* in_sizes, int n_in,
                              void* d_out, int out_size) {
    const float* x   = (const float*)d_in[0];   // [4, 2048, 4096] f32
    const int*   gi  = (const int*)d_in[1];     // [4096, 4096] i32
    const float* lut = (const float*)d_in[2];   // [65536] f32
    const float* sc  = (const float*)d_in[3];   // [4096, 1] f32
    float* out = (float*)d_out;                 // [4, 2048, 4096] f32

    (void)in_sizes; (void)n_in; (void)out_size;

    ghost_prep<<<24576, 256>>>((const int4*)gi, lut, sc, (const float4*)x);

    cudaFuncSetAttribute(ghost_gemm, cudaFuncAttributeMaxDynamicSharedMemorySize, SMEM_DYN);
    ghost_gemm<<<dim3(N_DIM / BN, M_DIM / BM), 256, SMEM_DYN>>>(out);
}